// round 1
// baseline (speedup 1.0000x reference)
#include <cuda_runtime.h>

// SelfAttention: B=4, S=4096, D_MODEL=1024, D_OUT=64
// Stage 1: proj_kernel computes q/k/v = X @ W + b into g_qkv (tf32 mma, fp32 accum)
// Stage 2: attn_kernel does flash-style attention (tf32 mma, online softmax)

#define BATCH 4
#define SEQ 4096
#define DMODEL 1024
#define DOUT 64
#define LOG2E 1.4426950408889634f

__device__ float g_qkv[3][(size_t)BATCH * SEQ * DOUT];

__device__ __forceinline__ unsigned f2tf(float f) {
    unsigned u;
    asm("cvt.rna.tf32.f32 %0, %1;" : "=r"(u) : "f"(f));
    return u;
}
__device__ __forceinline__ float ex2(float x) {
    float y;
    asm("ex2.approx.f32 %0, %1;" : "=f"(y) : "f"(x));
    return y;
}
// D += A(16x8, tf32, row) * B(8x8, tf32, col), fp32 accumulate
__device__ __forceinline__ void mma8(float* c, const unsigned* a, const unsigned* b) {
    asm volatile(
        "mma.sync.aligned.m16n8k8.row.col.f32.tf32.tf32.f32 "
        "{%0,%1,%2,%3},{%4,%5,%6,%7},{%8,%9},{%0,%1,%2,%3};"
        : "+f"(c[0]), "+f"(c[1]), "+f"(c[2]), "+f"(c[3])
        : "r"(a[0]), "r"(a[1]), "r"(a[2]), "r"(a[3]), "r"(b[0]), "r"(b[1]));
}

// ---------------------------------------------------------------------------
// Projection: out[r][n] = sum_k X[r][k] * W[k][n] + bias[n]
// Grid: (128 row-tiles, 3 projections). Block: 256 threads (8 warps).
// CTA tile: 128 rows x 64 cols, K chunked by 32.
// ---------------------------------------------------------------------------
__global__ __launch_bounds__(256, 1) void proj_kernel(
    const float* __restrict__ q, const float* __restrict__ k, const float* __restrict__ v,
    const float* __restrict__ Wq, const float* __restrict__ bq,
    const float* __restrict__ Wk, const float* __restrict__ bk,
    const float* __restrict__ Wv, const float* __restrict__ bv)
{
    const int p = blockIdx.y;
    const float* X = (p == 0) ? q : (p == 1) ? k : v;
    const float* W = (p == 0) ? Wq : (p == 1) ? Wk : Wv;
    const float* B = (p == 0) ? bq : (p == 1) ? bk : bv;
    float* out = g_qkv[p];

    __shared__ float Xs[128][36];  // stride 36 (== 4 mod 32): frag LDS conflict-free
    __shared__ float Ws[32][68];   // stride 68 (== 4 mod 32)

    const int tid = threadIdx.x;
    const int lane = tid & 31, warp = tid >> 5;
    const int g = lane >> 2, t4 = lane & 3;
    const int rowbase = blockIdx.x * 128;

    float c[8][4];
#pragma unroll
    for (int i = 0; i < 8; i++)
#pragma unroll
        for (int j = 0; j < 4; j++) c[i][j] = 0.f;

    for (int k0 = 0; k0 < DMODEL; k0 += 32) {
        __syncthreads();
        // X chunk: 128 x 32 floats (converted to tf32 bits at store)
#pragma unroll
        for (int i = 0; i < 4; i++) {
            int idx = tid + i * 256;            // 0..1023
            int r = idx >> 3, c4 = idx & 7;     // r 0..127, c4 0..7
            float4 xv = *(const float4*)(X + (size_t)(rowbase + r) * DMODEL + k0 + c4 * 4);
            float4 xs;
            xs.x = __uint_as_float(f2tf(xv.x));
            xs.y = __uint_as_float(f2tf(xv.y));
            xs.z = __uint_as_float(f2tf(xv.z));
            xs.w = __uint_as_float(f2tf(xv.w));
            *(float4*)&Xs[r][c4 * 4] = xs;
        }
        // W chunk: 32 x 64 floats
#pragma unroll
        for (int i = 0; i < 2; i++) {
            int idx = tid + i * 256;            // 0..511
            int r = idx >> 4, c4 = idx & 15;    // r 0..31, c4 0..15
            float4 wv = *(const float4*)(W + (size_t)(k0 + r) * DOUT + c4 * 4);
            float4 ws;
            ws.x = __uint_as_float(f2tf(wv.x));
            ws.y = __uint_as_float(f2tf(wv.y));
            ws.z = __uint_as_float(f2tf(wv.z));
            ws.w = __uint_as_float(f2tf(wv.w));
            *(float4*)&Ws[r][c4 * 4] = ws;
        }
        __syncthreads();

        const int r0 = warp * 16 + g;
#pragma unroll
        for (int kk = 0; kk < 4; kk++) {
            unsigned a[4];
            a[0] = __float_as_uint(Xs[r0][kk * 8 + t4]);
            a[1] = __float_as_uint(Xs[r0 + 8][kk * 8 + t4]);
            a[2] = __float_as_uint(Xs[r0][kk * 8 + t4 + 4]);
            a[3] = __float_as_uint(Xs[r0 + 8][kk * 8 + t4 + 4]);
#pragma unroll
            for (int nt = 0; nt < 8; nt++) {
                unsigned b[2];
                b[0] = __float_as_uint(Ws[kk * 8 + t4][nt * 8 + g]);
                b[1] = __float_as_uint(Ws[kk * 8 + t4 + 4][nt * 8 + g]);
                mma8(c[nt], a, b);
            }
        }
    }

    // Epilogue: add bias, store float2 pairs
    const int gr0 = rowbase + warp * 16 + g;
#pragma unroll
    for (int nt = 0; nt < 8; nt++) {
        int col = nt * 8 + t4 * 2;
        float b0 = B[col], b1 = B[col + 1];
        *(float2*)&out[(size_t)gr0 * DOUT + col] = make_float2(c[nt][0] + b0, c[nt][1] + b1);
        *(float2*)&out[(size_t)(gr0 + 8) * DOUT + col] = make_float2(c[nt][2] + b0, c[nt][3] + b1);
    }
}

// ---------------------------------------------------------------------------
// Attention: flash-style. Grid (SEQ/128, BATCH). Block 256 (8 warps x 16 rows).
// BM=128 query rows per CTA, BN=64 keys per block iteration.
// Q frags in registers (pre-scaled by 1/8), K/V through static smem (tf32).
// ---------------------------------------------------------------------------
__global__ __launch_bounds__(256, 1) void attn_kernel(float* __restrict__ out)
{
    const int b = blockIdx.y;
    const int qt = blockIdx.x;

    __shared__ float Ks[64][68];
    __shared__ float Vs[64][68];

    const int tid = threadIdx.x;
    const int lane = tid & 31, warp = tid >> 5;
    const int g = lane >> 2, t4 = lane & 3;

    const float* Q = g_qkv[0] + (size_t)b * SEQ * DOUT;
    const float* K = g_qkv[1] + (size_t)b * SEQ * DOUT;
    const float* V = g_qkv[2] + (size_t)b * SEQ * DOUT;

    // Preload Q fragments (A layout), scaled by 1/sqrt(64) = 0.125
    unsigned aq[8][4];
    const int qr0 = qt * 128 + warp * 16 + g;
#pragma unroll
    for (int ks = 0; ks < 8; ks++) {
        int cb = ks * 8 + t4;
        aq[ks][0] = f2tf(Q[(size_t)qr0 * DOUT + cb] * 0.125f);
        aq[ks][1] = f2tf(Q[(size_t)(qr0 + 8) * DOUT + cb] * 0.125f);
        aq[ks][2] = f2tf(Q[(size_t)qr0 * DOUT + cb + 4] * 0.125f);
        aq[ks][3] = f2tf(Q[(size_t)(qr0 + 8) * DOUT + cb + 4] * 0.125f);
    }

    float o[8][4];
#pragma unroll
    for (int i = 0; i < 8; i++)
#pragma unroll
        for (int j = 0; j < 4; j++) o[i][j] = 0.f;
    float m0 = -1e30f, m1 = -1e30f, l0 = 0.f, l1 = 0.f;

    for (int kb = 0; kb < SEQ / 64; kb++) {
        __syncthreads();
        // Load K,V block: 64 x 64 each, tf32-converted at store
#pragma unroll
        for (int i = 0; i < 4; i++) {
            int idx = tid + i * 256;          // 0..1023
            int r = idx >> 4, c4 = idx & 15;  // r 0..63, c4 0..15
            size_t goff = ((size_t)kb * 64 + r) * DOUT + c4 * 4;
            float4 kv = *(const float4*)(K + goff);
            float4 ks;
            ks.x = __uint_as_float(f2tf(kv.x));
            ks.y = __uint_as_float(f2tf(kv.y));
            ks.z = __uint_as_float(f2tf(kv.z));
            ks.w = __uint_as_float(f2tf(kv.w));
            *(float4*)&Ks[r][c4 * 4] = ks;
            float4 vv = *(const float4*)(V + goff);
            float4 vs;
            vs.x = __uint_as_float(f2tf(vv.x));
            vs.y = __uint_as_float(f2tf(vv.y));
            vs.z = __uint_as_float(f2tf(vv.z));
            vs.w = __uint_as_float(f2tf(vv.w));
            *(float4*)&Vs[r][c4 * 4] = vs;
        }
        __syncthreads();

        // S = Q * K^T (scaled): s[nt] covers key cols [nt*8, nt*8+8)
        float s[8][4];
#pragma unroll
        for (int i = 0; i < 8; i++)
#pragma unroll
            for (int j = 0; j < 4; j++) s[i][j] = 0.f;

#pragma unroll
        for (int ks = 0; ks < 8; ks++) {
#pragma unroll
            for (int nt = 0; nt < 8; nt++) {
                unsigned bb[2];
                bb[0] = __float_as_uint(Ks[nt * 8 + g][ks * 8 + t4]);
                bb[1] = __float_as_uint(Ks[nt * 8 + g][ks * 8 + t4 + 4]);
                mma8(s[nt], aq[ks], bb);
            }
        }

        // Online softmax: rows (g) -> regs {0,1}, (g+8) -> regs {2,3}
        float rmax0 = -1e30f, rmax1 = -1e30f;
#pragma unroll
        for (int nt = 0; nt < 8; nt++) {
            rmax0 = fmaxf(rmax0, fmaxf(s[nt][0], s[nt][1]));
            rmax1 = fmaxf(rmax1, fmaxf(s[nt][2], s[nt][3]));
        }
        rmax0 = fmaxf(rmax0, __shfl_xor_sync(0xffffffffu, rmax0, 1));
        rmax0 = fmaxf(rmax0, __shfl_xor_sync(0xffffffffu, rmax0, 2));
        rmax1 = fmaxf(rmax1, __shfl_xor_sync(0xffffffffu, rmax1, 1));
        rmax1 = fmaxf(rmax1, __shfl_xor_sync(0xffffffffu, rmax1, 2));

        float nm0 = fmaxf(m0, rmax0), nm1 = fmaxf(m1, rmax1);
        float corr0 = ex2((m0 - nm0) * LOG2E);
        float corr1 = ex2((m1 - nm1) * LOG2E);

        float rs0 = 0.f, rs1 = 0.f;
#pragma unroll
        for (int nt = 0; nt < 8; nt++) {
            s[nt][0] = ex2((s[nt][0] - nm0) * LOG2E);
            s[nt][1] = ex2((s[nt][1] - nm0) * LOG2E);
            s[nt][2] = ex2((s[nt][2] - nm1) * LOG2E);
            s[nt][3] = ex2((s[nt][3] - nm1) * LOG2E);
            rs0 += s[nt][0] + s[nt][1];
            rs1 += s[nt][2] + s[nt][3];
        }
        rs0 += __shfl_xor_sync(0xffffffffu, rs0, 1);
        rs0 += __shfl_xor_sync(0xffffffffu, rs0, 2);
        rs1 += __shfl_xor_sync(0xffffffffu, rs1, 1);
        rs1 += __shfl_xor_sync(0xffffffffu, rs1, 2);

        l0 = l0 * corr0 + rs0;
        l1 = l1 * corr1 + rs1;
        m0 = nm0;
        m1 = nm1;

#pragma unroll
        for (int nt = 0; nt < 8; nt++) {
            o[nt][0] *= corr0;
            o[nt][1] *= corr0;
            o[nt][2] *= corr1;
            o[nt][3] *= corr1;
        }

        // O += P * V. P is in C layout; permute to A layout via quad shuffles.
        const int src0 = (lane & 28) | (t4 >> 1);
        const int src1 = src0 + 2;
#pragma unroll
        for (int kt = 0; kt < 8; kt++) {
            unsigned p0 = f2tf(s[kt][0]), p1 = f2tf(s[kt][1]);
            unsigned p2 = f2tf(s[kt][2]), p3 = f2tf(s[kt][3]);
            unsigned a[4];
            unsigned u0, u1;
            u0 = __shfl_sync(0xffffffffu, p0, src0);
            u1 = __shfl_sync(0xffffffffu, p1, src0);
            a[0] = (t4 & 1) ? u1 : u0;
            u0 = __shfl_sync(0xffffffffu, p0, src1);
            u1 = __shfl_sync(0xffffffffu, p1, src1);
            a[2] = (t4 & 1) ? u1 : u0;
            u0 = __shfl_sync(0xffffffffu, p2, src0);
            u1 = __shfl_sync(0xffffffffu, p3, src0);
            a[1] = (t4 & 1) ? u1 : u0;
            u0 = __shfl_sync(0xffffffffu, p2, src1);
            u1 = __shfl_sync(0xffffffffu, p3, src1);
            a[3] = (t4 & 1) ? u1 : u0;

#pragma unroll
            for (int nt = 0; nt < 8; nt++) {
                unsigned bb[2];
                bb[0] = __float_as_uint(Vs[kt * 8 + t4][nt * 8 + g]);
                bb[1] = __float_as_uint(Vs[kt * 8 + t4 + 4][nt * 8 + g]);
                mma8(o[nt], a, bb);
            }
        }
    }

    // Epilogue: normalize and store
    const float inv0 = 1.f / l0;
    const float inv1 = 1.f / l1;
    const size_t orow0 = (size_t)b * SEQ + qt * 128 + warp * 16 + g;
#pragma unroll
    for (int nt = 0; nt < 8; nt++) {
        int col = nt * 8 + t4 * 2;
        *(float2*)&out[orow0 * DOUT + col] =
            make_float2(o[nt][0] * inv0, o[nt][1] * inv0);
        *(float2*)&out[(orow0 + 8) * DOUT + col] =
            make_float2(o[nt][2] * inv1, o[nt][3] * inv1);
    }
}

extern "C" void kernel_launch(void* const* d_in, const int* in_sizes, int n_in,
                              void* d_out, int out_size) {
    (void)in_sizes; (void)n_in; (void)out_size;
    const float* q  = (const float*)d_in[0];
    const float* k  = (const float*)d_in[1];
    const float* v  = (const float*)d_in[2];
    const float* Wq = (const float*)d_in[3];
    const float* bq = (const float*)d_in[4];
    const float* Wk = (const float*)d_in[5];
    const float* bk = (const float*)d_in[6];
    const float* Wv = (const float*)d_in[7];
    const float* bv = (const float*)d_in[8];

    proj_kernel<<<dim3(BATCH * SEQ / 128, 3), 256>>>(q, k, v, Wq, bq, Wk, bk, Wv, bv);
    attn_kernel<<<dim3(SEQ / 128, BATCH), 256>>>((float*)d_out);
}